// round 3
// baseline (speedup 1.0000x reference)
#include <cuda_runtime.h>
#include <cuda_bf16.h>

// ===================== problem constants =====================
#define NN_MAX   50000
#define EE_MAX   800000
#define IN_DIM   768
#define FEAT     128      // H*D for both layers (4*32 and 1*128)

// ===================== scratch (static device globals; no allocs) ==========
__device__ float g_z   [NN_MAX * FEAT];   // z1, then reused for z2
__device__ float g_h1  [NN_MAX * FEAT];   // elu(layer1 out)
__device__ float g_Wp  [IN_DIM * FEAT];   // packed W1
__device__ float g_ssrc[NN_MAX * 4];
__device__ float g_sdst[NN_MAX * 4];
__device__ int   g_deg [NN_MAX];          // histogram, then reused as cursor
__device__ int   g_rp  [NN_MAX + 1];      // CSR row_ptr (by dst)
__device__ int   g_csr [EE_MAX];          // src ids sorted by dst

// ===================== small utility kernels =====================
__global__ void zero_int_kernel(int* __restrict__ p, int n) {
    int i = blockIdx.x * blockDim.x + threadIdx.x;
    if (i < n) p[i] = 0;
}

// W1[h][i][o] -> Wp[i][h*32+o]
__global__ void pack_w1_kernel(const float* __restrict__ W1, float* __restrict__ Wp) {
    int i = blockIdx.x * blockDim.x + threadIdx.x;
    if (i >= IN_DIM * FEAT) return;
    int row = i / FEAT;           // k index (0..767)
    int c   = i - row * FEAT;     // 0..127
    int hh  = c >> 5;             // head
    int oo  = c & 31;             // out dim within head
    Wp[i] = W1[(hh * IN_DIM + row) * 32 + oo];
}

__global__ void hist_kernel(const int* __restrict__ dst, int* __restrict__ deg, int E) {
    int i = blockIdx.x * blockDim.x + threadIdx.x;
    if (i < E) atomicAdd(&deg[dst[i]], 1);
}

// single-block exclusive scan over N=50000 (chunked + block scan)
__global__ void scan_kernel(const int* __restrict__ deg, int* __restrict__ rowptr, int N) {
    __shared__ int sums[1024];
    int tid  = threadIdx.x;
    int per  = (N + 1023) / 1024;
    int start = tid * per;
    int stop  = start + per; if (stop > N) stop = N;
    int local = 0;
    for (int i = start; i < stop; ++i) local += deg[i];
    sums[tid] = local;
    __syncthreads();
    // inclusive Hillis-Steele scan
    for (int off = 1; off < 1024; off <<= 1) {
        int v = (tid >= off) ? sums[tid - off] : 0;
        __syncthreads();
        sums[tid] += v;
        __syncthreads();
    }
    int run = sums[tid] - local;   // exclusive prefix of this chunk
    for (int i = start; i < stop; ++i) { rowptr[i] = run; run += deg[i]; }
    if (tid == 0) rowptr[N] = sums[1023];
}

__global__ void scatter_kernel(const int* __restrict__ src, const int* __restrict__ dst,
                               const int* __restrict__ rowptr, int* __restrict__ cursor,
                               int* __restrict__ csr, int E) {
    int i = blockIdx.x * blockDim.x + threadIdx.x;
    if (i >= E) return;
    int d = dst[i];
    int p = atomicAdd(&cursor[d], 1);
    csr[rowptr[d] + p] = src[i];
}

// ===================== GEMM: C[N,128] = A[N,K] @ B[K,128] (fp32 SIMT) =====
// BM=128, BN=128, BK=8, 256 threads, 8x8 outputs/thread.
// Double-buffered smem, register prefetch, ONE __syncthreads per k-tile.
template <int K>
__global__ __launch_bounds__(256)
void gemm128_kernel(const float* __restrict__ A, const float* __restrict__ B,
                    float* __restrict__ C, int N) {
    __shared__ float As[2][8][128];  // [buf][k][m]
    __shared__ float Bs[2][8][128];  // [buf][k][n]
    const int tid  = threadIdx.x;
    const int tx   = tid & 15;       // col group: cols tx*8 .. tx*8+7
    const int ty   = tid >> 4;       // row group: rows ty*8 .. ty*8+7
    const int row0 = blockIdx.x * 128;

    const int ar = tid >> 1;         // 0..127  (A tile row)
    const int ac = (tid & 1) * 4;    // 0 or 4  (A tile k-col)
    const int br = tid >> 5;         // 0..7    (B tile k-row)
    const int bc = (tid & 31) * 4;   // 0..124  (B tile col)

    float acc[8][8];
#pragma unroll
    for (int i = 0; i < 8; ++i)
#pragma unroll
        for (int j = 0; j < 8; ++j) acc[i][j] = 0.f;

    const int  arow  = row0 + ar;
    const bool a_ok  = (arow < N);
    const long abase = (long)arow * K + ac;

    const int nkt = K / 8;

    // preload tile 0 into buffer 0
    {
        float4 av = make_float4(0.f, 0.f, 0.f, 0.f);
        if (a_ok) av = *(const float4*)&A[abase];
        As[0][ac + 0][ar] = av.x;
        As[0][ac + 1][ar] = av.y;
        As[0][ac + 2][ar] = av.z;
        As[0][ac + 3][ar] = av.w;
        *(float4*)&Bs[0][br][bc] = *(const float4*)&B[br * 128 + bc];
    }
    __syncthreads();

    for (int kt = 0; kt < nkt; ++kt) {
        const int cur = kt & 1;
        float4 av_n = make_float4(0.f, 0.f, 0.f, 0.f);
        float4 bv_n;
        const bool more = (kt + 1 < nkt);
        if (more) {
            // issue prefetch loads; latency overlapped with FFMA below
            if (a_ok) av_n = *(const float4*)&A[abase + (kt + 1) * 8];
            bv_n = *(const float4*)&B[((kt + 1) * 8 + br) * 128 + bc];
        }
#pragma unroll
        for (int k = 0; k < 8; ++k) {
            float4 a0 = *(const float4*)&As[cur][k][ty * 8];
            float4 a1 = *(const float4*)&As[cur][k][ty * 8 + 4];
            float4 b0 = *(const float4*)&Bs[cur][k][tx * 8];
            float4 b1 = *(const float4*)&Bs[cur][k][tx * 8 + 4];
            float ra[8] = {a0.x, a0.y, a0.z, a0.w, a1.x, a1.y, a1.z, a1.w};
            float rb[8] = {b0.x, b0.y, b0.z, b0.w, b1.x, b1.y, b1.z, b1.w};
#pragma unroll
            for (int i = 0; i < 8; ++i)
#pragma unroll
                for (int j = 0; j < 8; ++j) acc[i][j] += ra[i] * rb[j];
        }
        if (more) {
            const int nxt = cur ^ 1;
            // safe: smem[nxt] readers finished at the barrier ending iter kt-1
            As[nxt][ac + 0][ar] = av_n.x;
            As[nxt][ac + 1][ar] = av_n.y;
            As[nxt][ac + 2][ar] = av_n.z;
            As[nxt][ac + 3][ar] = av_n.w;
            *(float4*)&Bs[nxt][br][bc] = bv_n;
            __syncthreads();
        }
    }
#pragma unroll
    for (int i = 0; i < 8; ++i) {
        int r = row0 + ty * 8 + i;
        if (r < N) {
            *(float4*)&C[(long)r * 128 + tx * 8] =
                make_float4(acc[i][0], acc[i][1], acc[i][2], acc[i][3]);
            *(float4*)&C[(long)r * 128 + tx * 8 + 4] =
                make_float4(acc[i][4], acc[i][5], acc[i][6], acc[i][7]);
        }
    }
}

// ===================== attention scores: s_src/s_dst per (node, head) =====
// warp per node; lane owns 4 consecutive feature dims
template <int H, int D>
__global__ __launch_bounds__(256)
void score_kernel(const float* __restrict__ z, const float* __restrict__ a,
                  float* __restrict__ ssrc, float* __restrict__ sdst, int N) {
    int warp = (blockIdx.x * blockDim.x + threadIdx.x) >> 5;
    int lane = threadIdx.x & 31;
    if (warp >= N) return;
    int n  = warp;
    int j0 = lane * 4;
    int h  = j0 / D;
    int dd = j0 % D;
    float4 zv = *(const float4*)&z[(long)n * FEAT + j0];
    float4 as = *(const float4*)&a[h * 2 * D + dd];
    float4 ad = *(const float4*)&a[h * 2 * D + D + dd];
    float ps = zv.x * as.x + zv.y * as.y + zv.z * as.z + zv.w * as.w;
    float pd = zv.x * ad.x + zv.y * ad.y + zv.z * ad.z + zv.w * ad.w;
    const int G = D / 4;   // lanes per head group (8 or 32), aligned groups
#pragma unroll
    for (int o = G / 2; o; o >>= 1) {
        ps += __shfl_xor_sync(0xffffffffu, ps, o);
        pd += __shfl_xor_sync(0xffffffffu, pd, o);
    }
    if (dd == 0) {
        ssrc[n * H + h] = ps;
        sdst[n * H + h] = pd;
    }
}

// ===================== GAT aggregation: warp per dst node, no atomics =====
// Online (flash) softmax: ONE gather pass for max+denom, one pass for weighted sum.
__device__ __forceinline__ float lrelu(float x) { return x > 0.f ? x : 0.01f * x; }

template <int H, int D, bool DO_ELU>
__global__ __launch_bounds__(256)
void gat_aggregate_kernel(const float* __restrict__ z,
                          const float* __restrict__ ssrc,
                          const float* __restrict__ sdst,
                          const int* __restrict__ rowptr,
                          const int* __restrict__ csr,
                          float* __restrict__ out, int N) {
    int warp = (blockIdx.x * blockDim.x + threadIdx.x) >> 5;
    int lane = threadIdx.x & 31;
    if (warp >= N) return;
    int n   = warp;
    int beg = rowptr[n];
    int end = rowptr[n + 1];

    float sd[H];
#pragma unroll
    for (int h = 0; h < H; ++h) sd[h] = sdst[n * H + h];

    // ---- pass 1 (online): running max mx and running sum dn per head ----
    float mx[H], dn[H];
#pragma unroll
    for (int h = 0; h < H; ++h) { mx[h] = -3.0e38f; dn[h] = 0.f; }
    for (int i = beg + lane; i < end; i += 32) {
        int s = csr[i];
#pragma unroll
        for (int h = 0; h < H; ++h) {
            float e  = lrelu(ssrc[s * H + h] + sd[h]);
            float m2 = fmaxf(mx[h], e);
            dn[h] = dn[h] * __expf(mx[h] - m2) + __expf(e - m2);
            mx[h] = m2;
        }
    }
    // warp-combine (m, d) pairs
#pragma unroll
    for (int h = 0; h < H; ++h) {
#pragma unroll
        for (int o = 16; o; o >>= 1) {
            float mo = __shfl_xor_sync(0xffffffffu, mx[h], o);
            float do_ = __shfl_xor_sync(0xffffffffu, dn[h], o);
            float m2 = fmaxf(mx[h], mo);
            dn[h] = dn[h] * __expf(mx[h] - m2) + do_ * __expf(mo - m2);
            mx[h] = m2;
        }
    }
    float rdn[H];
#pragma unroll
    for (int h = 0; h < H; ++h) rdn[h] = 1.0f / fmaxf(dn[h], 1e-9f);

    // ---- pass 2: out = sum alpha * z[src]; lane owns 4 output dims ----
    const int j0 = lane * 4;
    const int hh = j0 / D;
    float4 acc = make_float4(0.f, 0.f, 0.f, 0.f);
    for (int i = beg; i < end; ++i) {
        int s = csr[i];                                  // uniform across warp
        float e  = lrelu(ssrc[s * H + hh] + sd[hh]);
        float al = __expf(e - mx[hh]) * rdn[hh];
        float4 zv = *(const float4*)&z[(long)s * FEAT + j0];
        acc.x += al * zv.x;
        acc.y += al * zv.y;
        acc.z += al * zv.z;
        acc.w += al * zv.w;
    }
    if (DO_ELU) {
        acc.x = acc.x > 0.f ? acc.x : (__expf(acc.x) - 1.f);
        acc.y = acc.y > 0.f ? acc.y : (__expf(acc.y) - 1.f);
        acc.z = acc.z > 0.f ? acc.z : (__expf(acc.z) - 1.f);
        acc.w = acc.w > 0.f ? acc.w : (__expf(acc.w) - 1.f);
    }
    *(float4*)&out[(long)n * FEAT + j0] = acc;
}

// ===================== host launcher =====================
extern "C" void kernel_launch(void* const* d_in, const int* in_sizes, int n_in,
                              void* d_out, int out_size) {
    const float* h   = (const float*)d_in[0];
    const float* W1  = (const float*)d_in[1];
    const float* a1  = (const float*)d_in[2];
    const float* W2  = (const float*)d_in[3];
    const float* a2  = (const float*)d_in[4];
    const int*   src = (const int*)d_in[5];
    const int*   dst = (const int*)d_in[6];
    float*       out = (float*)d_out;

    const int N = in_sizes[0] / IN_DIM;   // 50000
    const int E = in_sizes[5];            // 800000

    float *pz, *ph1, *pwp, *pss, *psd;
    int *pdeg, *prp, *pcsr;
    cudaGetSymbolAddress((void**)&pz,   g_z);
    cudaGetSymbolAddress((void**)&ph1,  g_h1);
    cudaGetSymbolAddress((void**)&pwp,  g_Wp);
    cudaGetSymbolAddress((void**)&pss,  g_ssrc);
    cudaGetSymbolAddress((void**)&psd,  g_sdst);
    cudaGetSymbolAddress((void**)&pdeg, g_deg);
    cudaGetSymbolAddress((void**)&prp,  g_rp);
    cudaGetSymbolAddress((void**)&pcsr, g_csr);

    const int TB = 256;
    const int warp_blocks = (N * 32 + TB - 1) / TB;

    // ---- build CSR (by dst); shared by both layers ----
    zero_int_kernel<<<(N + TB - 1) / TB, TB>>>(pdeg, N);
    hist_kernel<<<(E + TB - 1) / TB, TB>>>(dst, pdeg, E);
    scan_kernel<<<1, 1024>>>(pdeg, prp, N);
    zero_int_kernel<<<(N + TB - 1) / TB, TB>>>(pdeg, N);   // reuse as cursor
    scatter_kernel<<<(E + TB - 1) / TB, TB>>>(src, dst, prp, pdeg, pcsr, E);

    // ---- layer 1 ----
    pack_w1_kernel<<<(IN_DIM * FEAT + TB - 1) / TB, TB>>>(W1, pwp);
    gemm128_kernel<IN_DIM><<<(N + 127) / 128, TB>>>(h, pwp, pz, N);
    score_kernel<4, 32><<<warp_blocks, TB>>>(pz, a1, pss, psd, N);
    gat_aggregate_kernel<4, 32, true><<<warp_blocks, TB>>>(pz, pss, psd, prp, pcsr, ph1, N);

    // ---- layer 2 (W2 is already [128,128] row-major for head 0) ----
    gemm128_kernel<FEAT><<<(N + 127) / 128, TB>>>(ph1, W2, pz, N);
    score_kernel<1, 128><<<warp_blocks, TB>>>(pz, a2, pss, psd, N);
    gat_aggregate_kernel<1, 128, false><<<warp_blocks, TB>>>(pz, pss, psd, prp, pcsr, out, N);
}

// round 4
// speedup vs baseline: 1.5474x; 1.5474x over previous
#include <cuda_runtime.h>
#include <cuda_bf16.h>
#include <cstdint>

// ===================== problem constants =====================
#define NN_MAX   50000
#define EE_MAX   800000
#define IN_DIM   768
#define FEAT     128      // H*D for both layers (4*32 and 1*128)

// ===================== scratch (static device globals; no allocs) ==========
__device__ float g_z   [NN_MAX * FEAT];   // z1, then reused for z2
__device__ float g_h1  [NN_MAX * FEAT];   // elu(layer1 out)
__device__ float g_Wp  [IN_DIM * FEAT];   // packed W1
__device__ float g_ssrc[NN_MAX * 4];
__device__ float g_sdst[NN_MAX * 4];
__device__ int   g_deg [NN_MAX];          // histogram, then reused as cursor
__device__ int   g_rp  [NN_MAX + 1];      // CSR row_ptr (by dst)
__device__ int   g_csr [EE_MAX];          // src ids sorted by dst

// ===================== small utility kernels =====================
__global__ void zero_int_kernel(int* __restrict__ p, int n) {
    int i = blockIdx.x * blockDim.x + threadIdx.x;
    if (i < n) p[i] = 0;
}

// W1[h][i][o] -> Wp[i][h*32+o]
__global__ void pack_w1_kernel(const float* __restrict__ W1, float* __restrict__ Wp) {
    int i = blockIdx.x * blockDim.x + threadIdx.x;
    if (i >= IN_DIM * FEAT) return;
    int row = i / FEAT;           // k index (0..767)
    int c   = i - row * FEAT;     // 0..127
    int hh  = c >> 5;             // head
    int oo  = c & 31;             // out dim within head
    Wp[i] = W1[(hh * IN_DIM + row) * 32 + oo];
}

__global__ void hist_kernel(const int* __restrict__ dst, int* __restrict__ deg, int E) {
    int i = blockIdx.x * blockDim.x + threadIdx.x;
    if (i < E) atomicAdd(&deg[dst[i]], 1);
}

// single-block exclusive scan over N=50000 (chunked + block scan)
__global__ void scan_kernel(const int* __restrict__ deg, int* __restrict__ rowptr, int N) {
    __shared__ int sums[1024];
    int tid  = threadIdx.x;
    int per  = (N + 1023) / 1024;
    int start = tid * per;
    int stop  = start + per; if (stop > N) stop = N;
    int local = 0;
    for (int i = start; i < stop; ++i) local += deg[i];
    sums[tid] = local;
    __syncthreads();
    for (int off = 1; off < 1024; off <<= 1) {
        int v = (tid >= off) ? sums[tid - off] : 0;
        __syncthreads();
        sums[tid] += v;
        __syncthreads();
    }
    int run = sums[tid] - local;
    for (int i = start; i < stop; ++i) { rowptr[i] = run; run += deg[i]; }
    if (tid == 0) rowptr[N] = sums[1023];
}

__global__ void scatter_kernel(const int* __restrict__ src, const int* __restrict__ dst,
                               const int* __restrict__ rowptr, int* __restrict__ cursor,
                               int* __restrict__ csr, int E) {
    int i = blockIdx.x * blockDim.x + threadIdx.x;
    if (i >= E) return;
    int d = dst[i];
    int p = atomicAdd(&cursor[d], 1);
    csr[rowptr[d] + p] = src[i];
}

// ===================== tf32 split helpers =====================
__device__ __forceinline__ uint32_t f2tf32(float x) {
    uint32_t r;
    asm("cvt.rna.tf32.f32 %0, %1;" : "=r"(r) : "f"(x));
    return r;
}
__device__ __forceinline__ void split_tf32(float x, uint32_t& hi, uint32_t& lo) {
    hi = f2tf32(x);
    lo = f2tf32(x - __uint_as_float(hi));
}
__device__ __forceinline__ void mma_tf32(float* c, const uint32_t* a, const uint32_t* b) {
    asm volatile(
        "mma.sync.aligned.m16n8k8.row.col.f32.tf32.tf32.f32 "
        "{%0,%1,%2,%3}, {%4,%5,%6,%7}, {%8,%9}, {%0,%1,%2,%3};"
        : "+f"(c[0]), "+f"(c[1]), "+f"(c[2]), "+f"(c[3])
        : "r"(a[0]), "r"(a[1]), "r"(a[2]), "r"(a[3]), "r"(b[0]), "r"(b[1]));
}

// ===================== GEMM: C[N,128] = A[N,K] @ B[K,128] ===============
// Tensor-core tf32 with 3-term error split (hi*hi + hi*lo + lo*hi).
// BM=128, BN=128, BK=8, 256 threads (8 warps, 2x4), warp tile 64x32.
// Smem stride 136 (== 8 mod 32): (t,g)->bank bijection => conflict-free LDS.
#define SMS 136
template <int K>
__global__ __launch_bounds__(256, 2)
void gemm_tc_kernel(const float* __restrict__ A, const float* __restrict__ B,
                    float* __restrict__ C, int N) {
    __shared__ uint32_t Ah[2][8][SMS];
    __shared__ uint32_t Al[2][8][SMS];
    __shared__ uint32_t Bh[2][8][SMS];
    __shared__ uint32_t Bl[2][8][SMS];

    const int tid  = threadIdx.x;
    const int lane = tid & 31;
    const int wid  = tid >> 5;       // 0..7
    const int wm   = wid & 1;        // m offset wm*64
    const int wn   = wid >> 1;       // n offset wn*32
    const int g    = lane >> 2;      // 0..7
    const int t    = lane & 3;       // 0..3

    const int row0 = blockIdx.x * 128;
    const int ar = tid >> 1;         // 0..127 (A tile row)
    const int ac = (tid & 1) * 4;    // 0 or 4 (A k-col)
    const int br = tid >> 5;         // 0..7   (B k-row)
    const int bc = (tid & 31) * 4;   // 0..124 (B col)

    float acc[4][4][4];
#pragma unroll
    for (int mt = 0; mt < 4; ++mt)
#pragma unroll
        for (int nt = 0; nt < 4; ++nt)
#pragma unroll
            for (int q = 0; q < 4; ++q) acc[mt][nt][q] = 0.f;

    const int  arow  = row0 + ar;
    const bool a_ok  = (arow < N);
    const long abase = (long)arow * K + ac;

    const int nkt = K / 8;

    // ---- preload tile 0 into buffer 0 ----
    {
        float4 av = make_float4(0.f, 0.f, 0.f, 0.f);
        if (a_ok) av = *(const float4*)&A[abase];
        float4 bv = *(const float4*)&B[br * 128 + bc];
        uint32_t h, l;
        float aa[4] = {av.x, av.y, av.z, av.w};
#pragma unroll
        for (int j = 0; j < 4; ++j) {
            split_tf32(aa[j], h, l);
            Ah[0][ac + j][ar] = h;
            Al[0][ac + j][ar] = l;
        }
        float bb[4] = {bv.x, bv.y, bv.z, bv.w};
        uint4 bhv, blv;
        split_tf32(bb[0], bhv.x, blv.x);
        split_tf32(bb[1], bhv.y, blv.y);
        split_tf32(bb[2], bhv.z, blv.z);
        split_tf32(bb[3], bhv.w, blv.w);
        *(uint4*)&Bh[0][br][bc] = bhv;
        *(uint4*)&Bl[0][br][bc] = blv;
    }
    __syncthreads();

    for (int kt = 0; kt < nkt; ++kt) {
        const int  cur  = kt & 1;
        const bool more = (kt + 1 < nkt);
        float4 av_n = make_float4(0.f, 0.f, 0.f, 0.f);
        float4 bv_n;
        if (more) {
            if (a_ok) av_n = *(const float4*)&A[abase + (kt + 1) * 8];
            bv_n = *(const float4*)&B[((kt + 1) * 8 + br) * 128 + bc];
        }

        // ---- compute on current buffer ----
        // preload B fragments (4 n-tiles x {b0,b1} x {hi,lo})
        uint32_t bh[4][2], bl[4][2];
#pragma unroll
        for (int nt = 0; nt < 4; ++nt) {
            int n = wn * 32 + nt * 8 + g;
            bh[nt][0] = Bh[cur][t    ][n];
            bh[nt][1] = Bh[cur][t + 4][n];
            bl[nt][0] = Bl[cur][t    ][n];
            bl[nt][1] = Bl[cur][t + 4][n];
        }
#pragma unroll
        for (int mt = 0; mt < 4; ++mt) {
            int m0 = wm * 64 + mt * 16 + g;
            uint32_t ah[4], al[4];
            ah[0] = Ah[cur][t    ][m0];
            ah[1] = Ah[cur][t    ][m0 + 8];
            ah[2] = Ah[cur][t + 4][m0];
            ah[3] = Ah[cur][t + 4][m0 + 8];
            al[0] = Al[cur][t    ][m0];
            al[1] = Al[cur][t    ][m0 + 8];
            al[2] = Al[cur][t + 4][m0];
            al[3] = Al[cur][t + 4][m0 + 8];
#pragma unroll
            for (int nt = 0; nt < 4; ++nt) {
                mma_tf32(acc[mt][nt], ah, bh[nt]);   // hi*hi
                mma_tf32(acc[mt][nt], ah, bl[nt]);   // hi*lo
                mma_tf32(acc[mt][nt], al, bh[nt]);   // lo*hi
            }
        }

        if (more) {
            const int nxt = cur ^ 1;
            uint32_t h, l;
            float aa[4] = {av_n.x, av_n.y, av_n.z, av_n.w};
#pragma unroll
            for (int j = 0; j < 4; ++j) {
                split_tf32(aa[j], h, l);
                Ah[nxt][ac + j][ar] = h;
                Al[nxt][ac + j][ar] = l;
            }
            float bb[4] = {bv_n.x, bv_n.y, bv_n.z, bv_n.w};
            uint4 bhv, blv;
            split_tf32(bb[0], bhv.x, blv.x);
            split_tf32(bb[1], bhv.y, blv.y);
            split_tf32(bb[2], bhv.z, blv.z);
            split_tf32(bb[3], bhv.w, blv.w);
            *(uint4*)&Bh[nxt][br][bc] = bhv;
            *(uint4*)&Bl[nxt][br][bc] = blv;
            __syncthreads();
        }
    }

    // ---- epilogue: C rows guarded against N ----
#pragma unroll
    for (int mt = 0; mt < 4; ++mt) {
        int r0 = row0 + wm * 64 + mt * 16 + g;
#pragma unroll
        for (int nt = 0; nt < 4; ++nt) {
            int n0 = wn * 32 + nt * 8 + 2 * t;
            if (r0 < N)
                *(float2*)&C[(long)r0 * 128 + n0] =
                    make_float2(acc[mt][nt][0], acc[mt][nt][1]);
            if (r0 + 8 < N)
                *(float2*)&C[(long)(r0 + 8) * 128 + n0] =
                    make_float2(acc[mt][nt][2], acc[mt][nt][3]);
        }
    }
}

// ===================== attention scores: s_src/s_dst per (node, head) =====
template <int H, int D>
__global__ __launch_bounds__(256)
void score_kernel(const float* __restrict__ z, const float* __restrict__ a,
                  float* __restrict__ ssrc, float* __restrict__ sdst, int N) {
    int warp = (blockIdx.x * blockDim.x + threadIdx.x) >> 5;
    int lane = threadIdx.x & 31;
    if (warp >= N) return;
    int n  = warp;
    int j0 = lane * 4;
    int h  = j0 / D;
    int dd = j0 % D;
    float4 zv = *(const float4*)&z[(long)n * FEAT + j0];
    float4 as = *(const float4*)&a[h * 2 * D + dd];
    float4 ad = *(const float4*)&a[h * 2 * D + D + dd];
    float ps = zv.x * as.x + zv.y * as.y + zv.z * as.z + zv.w * as.w;
    float pd = zv.x * ad.x + zv.y * ad.y + zv.z * ad.z + zv.w * ad.w;
    const int G = D / 4;
#pragma unroll
    for (int o = G / 2; o; o >>= 1) {
        ps += __shfl_xor_sync(0xffffffffu, ps, o);
        pd += __shfl_xor_sync(0xffffffffu, pd, o);
    }
    if (dd == 0) {
        ssrc[n * H + h] = ps;
        sdst[n * H + h] = pd;
    }
}

// ===================== GAT aggregation: warp per dst node, no atomics =====
__device__ __forceinline__ float lrelu(float x) { return x > 0.f ? x : 0.01f * x; }

template <int H, int D, bool DO_ELU>
__global__ __launch_bounds__(256)
void gat_aggregate_kernel(const float* __restrict__ z,
                          const float* __restrict__ ssrc,
                          const float* __restrict__ sdst,
                          const int* __restrict__ rowptr,
                          const int* __restrict__ csr,
                          float* __restrict__ out, int N) {
    int warp = (blockIdx.x * blockDim.x + threadIdx.x) >> 5;
    int lane = threadIdx.x & 31;
    if (warp >= N) return;
    int n   = warp;
    int beg = rowptr[n];
    int end = rowptr[n + 1];

    float sd[H];
#pragma unroll
    for (int h = 0; h < H; ++h) sd[h] = sdst[n * H + h];

    // ---- pass 1 (online): running max mx and running sum dn per head ----
    float mx[H], dn[H];
#pragma unroll
    for (int h = 0; h < H; ++h) { mx[h] = -3.0e38f; dn[h] = 0.f; }
    for (int i = beg + lane; i < end; i += 32) {
        int s = csr[i];
#pragma unroll
        for (int h = 0; h < H; ++h) {
            float e  = lrelu(ssrc[s * H + h] + sd[h]);
            float m2 = fmaxf(mx[h], e);
            dn[h] = dn[h] * __expf(mx[h] - m2) + __expf(e - m2);
            mx[h] = m2;
        }
    }
#pragma unroll
    for (int h = 0; h < H; ++h) {
#pragma unroll
        for (int o = 16; o; o >>= 1) {
            float mo  = __shfl_xor_sync(0xffffffffu, mx[h], o);
            float do_ = __shfl_xor_sync(0xffffffffu, dn[h], o);
            float m2 = fmaxf(mx[h], mo);
            dn[h] = dn[h] * __expf(mx[h] - m2) + do_ * __expf(mo - m2);
            mx[h] = m2;
        }
    }
    float rdn[H];
#pragma unroll
    for (int h = 0; h < H; ++h) rdn[h] = 1.0f / fmaxf(dn[h], 1e-9f);

    // ---- pass 2: out = sum alpha * z[src]; lane owns 4 output dims ----
    const int j0 = lane * 4;
    const int hh = j0 / D;
    float4 acc = make_float4(0.f, 0.f, 0.f, 0.f);
    for (int i = beg; i < end; ++i) {
        int s = csr[i];                                  // uniform across warp
        float e  = lrelu(ssrc[s * H + hh] + sd[hh]);
        float al = __expf(e - mx[hh]) * rdn[hh];
        float4 zv = *(const float4*)&z[(long)s * FEAT + j0];
        acc.x += al * zv.x;
        acc.y += al * zv.y;
        acc.z += al * zv.z;
        acc.w += al * zv.w;
    }
    if (DO_ELU) {
        acc.x = acc.x > 0.f ? acc.x : (__expf(acc.x) - 1.f);
        acc.y = acc.y > 0.f ? acc.y : (__expf(acc.y) - 1.f);
        acc.z = acc.z > 0.f ? acc.z : (__expf(acc.z) - 1.f);
        acc.w = acc.w > 0.f ? acc.w : (__expf(acc.w) - 1.f);
    }
    *(float4*)&out[(long)n * FEAT + j0] = acc;
}

// ===================== host launcher =====================
extern "C" void kernel_launch(void* const* d_in, const int* in_sizes, int n_in,
                              void* d_out, int out_size) {
    const float* h   = (const float*)d_in[0];
    const float* W1  = (const float*)d_in[1];
    const float* a1  = (const float*)d_in[2];
    const float* W2  = (const float*)d_in[3];
    const float* a2  = (const float*)d_in[4];
    const int*   src = (const int*)d_in[5];
    const int*   dst = (const int*)d_in[6];
    float*       out = (float*)d_out;

    const int N = in_sizes[0] / IN_DIM;   // 50000
    const int E = in_sizes[5];            // 800000

    float *pz, *ph1, *pwp, *pss, *psd;
    int *pdeg, *prp, *pcsr;
    cudaGetSymbolAddress((void**)&pz,   g_z);
    cudaGetSymbolAddress((void**)&ph1,  g_h1);
    cudaGetSymbolAddress((void**)&pwp,  g_Wp);
    cudaGetSymbolAddress((void**)&pss,  g_ssrc);
    cudaGetSymbolAddress((void**)&psd,  g_sdst);
    cudaGetSymbolAddress((void**)&pdeg, g_deg);
    cudaGetSymbolAddress((void**)&prp,  g_rp);
    cudaGetSymbolAddress((void**)&pcsr, g_csr);

    const int TB = 256;
    const int warp_blocks = (N * 32 + TB - 1) / TB;

    // ---- build CSR (by dst); shared by both layers ----
    zero_int_kernel<<<(N + TB - 1) / TB, TB>>>(pdeg, N);
    hist_kernel<<<(E + TB - 1) / TB, TB>>>(dst, pdeg, E);
    scan_kernel<<<1, 1024>>>(pdeg, prp, N);
    zero_int_kernel<<<(N + TB - 1) / TB, TB>>>(pdeg, N);   // reuse as cursor
    scatter_kernel<<<(E + TB - 1) / TB, TB>>>(src, dst, prp, pdeg, pcsr, E);

    // ---- layer 1 ----
    pack_w1_kernel<<<(IN_DIM * FEAT + TB - 1) / TB, TB>>>(W1, pwp);
    gemm_tc_kernel<IN_DIM><<<(N + 127) / 128, TB>>>(h, pwp, pz, N);
    score_kernel<4, 32><<<warp_blocks, TB>>>(pz, a1, pss, psd, N);
    gat_aggregate_kernel<4, 32, true><<<warp_blocks, TB>>>(pz, pss, psd, prp, pcsr, ph1, N);

    // ---- layer 2 (W2 is already [128,128] row-major for head 0) ----
    gemm_tc_kernel<FEAT><<<(N + 127) / 128, TB>>>(ph1, W2, pz, N);
    score_kernel<1, 128><<<warp_blocks, TB>>>(pz, a2, pss, psd, N);
    gat_aggregate_kernel<1, 128, false><<<warp_blocks, TB>>>(pz, pss, psd, prp, pcsr, out, N);
}